// round 1
// baseline (speedup 1.0000x reference)
#include <cuda_runtime.h>
#include <cuda_bf16.h>
#include <cstdint>
#include <math.h>

#define INST   64
#define NVOCAB 128
#define ED     256
#define HID    1024
#define BATCH  2048

// Precomputed HL[i] = E_l[i] @ W1[i], HR[i] = E_r[i] @ W1[i]  (fp32 scratch)
__device__ float g_HL[INST * NVOCAB * HID];
__device__ float g_HR[INST * NVOCAB * HID];

__device__ __forceinline__ uint32_t f2tf(float f) {
    uint32_t u;
    asm("cvt.rna.tf32.f32 %0, %1;" : "=r"(u) : "f"(f));
    return u;
}

__device__ __forceinline__ void mma8(float* c, const uint32_t* a, const uint32_t* b) {
    asm volatile(
        "mma.sync.aligned.m16n8k8.row.col.f32.tf32.tf32.f32 "
        "{%0,%1,%2,%3}, {%4,%5,%6,%7}, {%8,%9}, {%0,%1,%2,%3};"
        : "+f"(c[0]), "+f"(c[1]), "+f"(c[2]), "+f"(c[3])
        : "r"(a[0]), "r"(a[1]), "r"(a[2]), "r"(a[3]), "r"(b[0]), "r"(b[1]));
}

__device__ __forceinline__ float gelu_exact(float x) {
    return 0.5f * x * (1.0f + erff(x * 0.7071067811865476f));
}

// Shared tile strides (words). Chosen for conflict-free fragment loads:
//   A bank = (4*row + k) % 32  -> 32 distinct per a-frag quad group
//   B bank = (8*k + n) % 32    -> 32 distinct per b-frag
#define ASTR 36
#define BSTR 136

// ---------------------------------------------------------------------------
// Phase 1: HL/HR[i] = E[i] (128x256) @ W1[i] (256x1024), tf32 MMA, fp32 out
// grid (8 n-tiles, 64 instances, 2 sides), 256 threads
// ---------------------------------------------------------------------------
__global__ __launch_bounds__(256) void phase1_kernel(
    const float* __restrict__ El, const float* __restrict__ Er,
    const float* __restrict__ W1)
{
    __shared__ uint32_t A_s[128 * ASTR];
    __shared__ uint32_t B_s[32 * BSTR];

    const int nt = blockIdx.x, inst = blockIdx.y, side = blockIdx.z;
    const float* E   = (side ? Er : El) + inst * NVOCAB * ED;
    float*       Hst = (side ? g_HR : g_HL) + inst * NVOCAB * HID + nt * 128;
    const float* W   = W1 + inst * ED * HID + nt * 128;

    const int t    = threadIdx.x;
    const int lane = t & 31, w = t >> 5;
    const int wm = (w & 3) * 32, wn = (w >> 2) * 64;
    const int g = lane >> 2, tg = lane & 3;
    const int r = t >> 1, h = t & 1;

    float c[2][8][4];
#pragma unroll
    for (int s = 0; s < 2; s++)
#pragma unroll
        for (int q = 0; q < 8; q++)
#pragma unroll
            for (int v = 0; v < 4; v++) c[s][q][v] = 0.f;

    for (int kt = 0; kt < ED / 32; kt++) {
        const int k0 = kt * 32;
        // A tile: rows of E (row r, 16-float half h)
#pragma unroll
        for (int j = 0; j < 4; j++) {
            float4 v = *reinterpret_cast<const float4*>(E + r * ED + k0 + h * 16 + 4 * j);
            uint4 u = make_uint4(f2tf(v.x), f2tf(v.y), f2tf(v.z), f2tf(v.w));
            *reinterpret_cast<uint4*>(&A_s[r * ASTR + h * 16 + 4 * j]) = u;
        }
        // B tile: 32 k-rows x 128 n (warp writes contiguous 128 floats)
#pragma unroll
        for (int j = 0; j < 4; j++) {
            int id = t + 256 * j;
            int k = id >> 5, nc = (id & 31) * 4;
            float4 v = *reinterpret_cast<const float4*>(W + (k0 + k) * HID + nc);
            uint4 u = make_uint4(f2tf(v.x), f2tf(v.y), f2tf(v.z), f2tf(v.w));
            *reinterpret_cast<uint4*>(&B_s[k * BSTR + nc]) = u;
        }
        __syncthreads();
#pragma unroll
        for (int ks = 0; ks < 4; ks++) {
            const int kk = ks * 8;
            uint32_t af[2][4];
#pragma unroll
            for (int s = 0; s < 2; s++) {
                int r0 = wm + s * 16 + g;
                af[s][0] = A_s[r0 * ASTR + kk + tg];
                af[s][1] = A_s[(r0 + 8) * ASTR + kk + tg];
                af[s][2] = A_s[r0 * ASTR + kk + 4 + tg];
                af[s][3] = A_s[(r0 + 8) * ASTR + kk + 4 + tg];
            }
            uint32_t bf[8][2];
#pragma unroll
            for (int q = 0; q < 8; q++) {
                int nb = wn + q * 8 + g;
                bf[q][0] = B_s[(kk + tg) * BSTR + nb];
                bf[q][1] = B_s[(kk + 4 + tg) * BSTR + nb];
            }
#pragma unroll
            for (int s = 0; s < 2; s++)
#pragma unroll
                for (int q = 0; q < 8; q++)
                    mma8(c[s][q], af[s], bf[q]);
        }
        __syncthreads();
    }

#pragma unroll
    for (int s = 0; s < 2; s++) {
        int row = wm + s * 16 + g;
#pragma unroll
        for (int q = 0; q < 8; q++) {
            int col = wn + q * 8 + 2 * tg;
            *reinterpret_cast<float2*>(Hst + row * HID + col) =
                make_float2(c[s][q][0], c[s][q][1]);
            *reinterpret_cast<float2*>(Hst + (row + 8) * HID + col) =
                make_float2(c[s][q][2], c[s][q][3]);
        }
    }
}

// ---------------------------------------------------------------------------
// Phase 2: out[b,i,:] = gelu(HL[i,a1[b],:] + HR[i,a2[b],:]) @ W2[i] (1024x128)
// Fused gather + add + exact gelu + tf32 convert into A-tile staging.
// grid (16 m-tiles, 64 instances), 256 threads
// ---------------------------------------------------------------------------
__global__ __launch_bounds__(256) void phase2_kernel(
    const int* __restrict__ a, const float* __restrict__ W2,
    float* __restrict__ out)
{
    __shared__ uint32_t A_s[128 * ASTR];
    __shared__ uint32_t B_s[32 * BSTR];

    const int mt = blockIdx.x, inst = blockIdx.y;
    const float* W = W2 + inst * HID * NVOCAB;

    const int t    = threadIdx.x;
    const int lane = t & 31, w = t >> 5;
    const int wm = (w & 3) * 32, wn = (w >> 2) * 64;
    const int g = lane >> 2, tg = lane & 3;
    const int r = t >> 1, h = t & 1;

    const int b  = mt * 128 + r;
    const int i1 = a[2 * b];
    const int i2 = a[2 * b + 1];
    const float* pL = g_HL + ((size_t)inst * NVOCAB + i1) * HID + h * 16;
    const float* pR = g_HR + ((size_t)inst * NVOCAB + i2) * HID + h * 16;

    float c[2][8][4];
#pragma unroll
    for (int s = 0; s < 2; s++)
#pragma unroll
        for (int q = 0; q < 8; q++)
#pragma unroll
            for (int v = 0; v < 4; v++) c[s][q][v] = 0.f;

    for (int kt = 0; kt < HID / 32; kt++) {
        const int k0 = kt * 32;
        // A tile: gather two rows, add, exact gelu, tf32 convert
#pragma unroll
        for (int j = 0; j < 4; j++) {
            float4 vl = *reinterpret_cast<const float4*>(pL + k0 + 4 * j);
            float4 vr = *reinterpret_cast<const float4*>(pR + k0 + 4 * j);
            uint4 u;
            u.x = f2tf(gelu_exact(vl.x + vr.x));
            u.y = f2tf(gelu_exact(vl.y + vr.y));
            u.z = f2tf(gelu_exact(vl.z + vr.z));
            u.w = f2tf(gelu_exact(vl.w + vr.w));
            *reinterpret_cast<uint4*>(&A_s[r * ASTR + h * 16 + 4 * j]) = u;
        }
        // B tile: W2 chunk, 32 k-rows x 128 n
#pragma unroll
        for (int j = 0; j < 4; j++) {
            int id = t + 256 * j;
            int k = id >> 5, nc = (id & 31) * 4;
            float4 v = *reinterpret_cast<const float4*>(W + (k0 + k) * NVOCAB + nc);
            uint4 u = make_uint4(f2tf(v.x), f2tf(v.y), f2tf(v.z), f2tf(v.w));
            *reinterpret_cast<uint4*>(&B_s[k * BSTR + nc]) = u;
        }
        __syncthreads();
#pragma unroll
        for (int ks = 0; ks < 4; ks++) {
            const int kk = ks * 8;
            uint32_t af[2][4];
#pragma unroll
            for (int s = 0; s < 2; s++) {
                int r0 = wm + s * 16 + g;
                af[s][0] = A_s[r0 * ASTR + kk + tg];
                af[s][1] = A_s[(r0 + 8) * ASTR + kk + tg];
                af[s][2] = A_s[r0 * ASTR + kk + 4 + tg];
                af[s][3] = A_s[(r0 + 8) * ASTR + kk + 4 + tg];
            }
            uint32_t bf[8][2];
#pragma unroll
            for (int q = 0; q < 8; q++) {
                int nb = wn + q * 8 + g;
                bf[q][0] = B_s[(kk + tg) * BSTR + nb];
                bf[q][1] = B_s[(kk + 4 + tg) * BSTR + nb];
            }
#pragma unroll
            for (int s = 0; s < 2; s++)
#pragma unroll
                for (int q = 0; q < 8; q++)
                    mma8(c[s][q], af[s], bf[q]);
        }
        __syncthreads();
    }

    // Epilogue: out shape (BATCH, INST, NVOCAB) fp32
#pragma unroll
    for (int s = 0; s < 2; s++) {
        int rowb = mt * 128 + wm + s * 16 + g;
#pragma unroll
        for (int q = 0; q < 8; q++) {
            int col = wn + q * 8 + 2 * tg;
            *reinterpret_cast<float2*>(out + ((size_t)rowb * INST + inst) * NVOCAB + col) =
                make_float2(c[s][q][0], c[s][q][1]);
            *reinterpret_cast<float2*>(out + ((size_t)(rowb + 8) * INST + inst) * NVOCAB + col) =
                make_float2(c[s][q][2], c[s][q][3]);
        }
    }
}

extern "C" void kernel_launch(void* const* d_in, const int* in_sizes, int n_in,
                              void* d_out, int out_size)
{
    const int*   a  = (const int*)d_in[0];
    const float* El = (const float*)d_in[1];
    const float* Er = (const float*)d_in[2];
    const float* W1 = (const float*)d_in[3];
    const float* W2 = (const float*)d_in[4];
    float* out = (float*)d_out;

    dim3 g1(HID / 128, INST, 2);     // 8 n-tiles x 64 instances x {L,R}
    phase1_kernel<<<g1, 256>>>(El, Er, W1);

    dim3 g2(BATCH / 128, INST);      // 16 m-tiles x 64 instances
    phase2_kernel<<<g2, 256>>>(a, W2, out);
}